// round 2
// baseline (speedup 1.0000x reference)
#include <cuda_runtime.h>
#include <math.h>

// ---------------- problem constants ----------------
#define H     1900
#define FH    7600      // 4*H
#define KP    1904      // H padded to mult of 16 (K dim)
#define NP1   1920      // H padded to mult of 64 (N of gemm1)
#define NP2   7616      // 4H padded to mult of 64 (N of gemm2)
#define TSTEPS 153
#define TEPI   25
#define NB     256      // batch
#define BBATCH 512      // combined batch (tot rows 0..255, epi rows 256..511)
#define EMB    10
#define PADTOK 26

// ---------------- device scratch (static, no allocs) ----------------
__device__ __align__(16) float g_whn [KP * NP2];   // weight-normed wh, padded [1904][7616]
__device__ __align__(16) float g_wmhn[KP * NP1];   // weight-normed wmh, padded [1904][1920]
__device__ __align__(16) float g_wxn [EMB * NP2];  // [10][7616]
__device__ __align__(16) float g_wmxn[EMB * NP1];  // [10][1920]
__device__ __align__(16) float g_xs  [TSTEPS * BBATCH * EMB]; // embedded inputs per step
__device__ __align__(16) float g_h   [BBATCH * KP];
__device__ __align__(16) float g_c   [BBATCH * KP];
__device__ __align__(16) float g_m   [BBATCH * KP];
__device__ __align__(16) float g_z   [BBATCH * NP2];
__device__ __align__(16) float g_epih[NB * H];
__device__ __align__(16) float g_toth[NB * H];
__device__ int g_ei[NB];
__device__ int g_ti[NB];

// ---------------- weight norm: out = w * g / ||w_col||, into padded layout ----------------
__global__ void wnorm_kernel(const float* __restrict__ w, const float* __restrict__ g, int mode)
{
    float* out; int K, N, KPp, NPp;
    if (mode == 0)      { out = g_whn;  K = H;   N = FH; KPp = KP;  NPp = NP2; }
    else if (mode == 1) { out = g_wmhn; K = H;   N = H;  KPp = KP;  NPp = NP1; }
    else if (mode == 2) { out = g_wxn;  K = EMB; N = FH; KPp = EMB; NPp = NP2; }
    else                { out = g_wmxn; K = EMB; N = H;  KPp = EMB; NPp = NP1; }

    int j = blockIdx.x * blockDim.x + threadIdx.x;
    if (j >= NPp) return;
    if (j >= N) {
        for (int k = 0; k < KPp; k++) out[k * NPp + j] = 0.f;
        return;
    }
    float s = 0.f;
    for (int k = 0; k < K; k++) { float v = w[k * N + j]; s += v * v; }
    float scale = g[j] / sqrtf(fmaxf(s, 1e-12f));
    for (int k = 0; k < K; k++) out[k * NPp + j] = w[k * N + j] * scale;
    for (int k = K; k < KPp; k++) out[k * NPp + j] = 0.f;
}

// ---------------- lengths / extraction indices ----------------
__global__ void lengths_kernel(const int* __restrict__ epi, const int* __restrict__ lft,
                               const int* __restrict__ rgt)
{
    int b = blockIdx.x * blockDim.x + threadIdx.x;
    if (b >= NB) return;
    int el = 0; for (int t = 0; t < TEPI; t++) el += (epi[b * TEPI + t] != PADTOK);
    int ll = 0; for (int t = 0; t < 64;   t++) ll += (lft[b * 64 + t]   != PADTOK);
    int rl = 0; for (int t = 0; t < 64;   t++) rl += (rgt[b * 64 + t]   != PADTOK);
    ll = max(ll, 1); rl = max(rl, 1);
    int tl = el + ll + rl;
    g_ei[b] = min(max(el - 1, 0), TEPI - 1);
    g_ti[b] = min(max(tl - 1, 0), TSTEPS - 1);
}

// ---------------- embed inputs into per-step layout ----------------
__global__ void embed_kernel(const int* __restrict__ epi, const int* __restrict__ tot,
                             const float* __restrict__ embed)
{
    int idx = blockIdx.x * blockDim.x + threadIdx.x;
    const int totN = TSTEPS * NB * EMB;
    const int epiN = TEPI * NB * EMB;
    if (idx < totN) {
        int e = idx % EMB; int r = (idx / EMB) % NB; int t = idx / (EMB * NB);
        int tok = tot[r * TSTEPS + t];
        g_xs[(t * BBATCH + r) * EMB + e] = embed[tok * EMB + e];
    } else if (idx < totN + epiN) {
        int k = idx - totN;
        int e = k % EMB; int r = (k / EMB) % NB; int t = k / (EMB * NB);
        int tok = epi[r * TEPI + t];
        g_xs[(t * BBATCH + (NB + r)) * EMB + e] = embed[tok * EMB + e];
    }
}

// ---------------- init: zero h, c, m (incl. K pads) ----------------
__global__ void init_kernel()
{
    int idx = blockIdx.x * blockDim.x + threadIdx.x;
    if (idx < BBATCH * KP) { g_h[idx] = 0.f; g_c[idx] = 0.f; g_m[idx] = 0.f; }
}

// ---------------- step GEMM: C = A[Mt,KP] * B[KP,N], fused epilogues ----------------
// MODE 1: A=g_h, B=g_wmhn  -> m = (x@wmxn) * (h@wmhn)        (store to g_m, n<H)
// MODE 2: A=g_m, B=g_whn   -> z = (m@whn) + bias + x@wxn      (store to g_z, n<FH)
#define BM 128
#define BN 64
#define BKK 16

template <int MODE>
__global__ __launch_bounds__(256) void gemm_step(int t, const float* __restrict__ bias)
{
    const float* __restrict__ A  = (MODE == 1) ? g_h    : g_m;
    const float* __restrict__ Bm = (MODE == 1) ? g_wmhn : g_whn;
    const int ldb = (MODE == 1) ? NP1 : NP2;

    __shared__ __align__(16) float As[BKK][BM];
    __shared__ __align__(16) float Bs[BKK][BN];

    const int tid  = threadIdx.x;
    const int row0 = blockIdx.y * BM;
    const int col0 = blockIdx.x * BN;

    float acc[8][4];
#pragma unroll
    for (int i = 0; i < 8; i++)
#pragma unroll
        for (int j = 0; j < 4; j++) acc[i][j] = 0.f;

    const int aRow = tid >> 2;            // 0..63
    const int aCol = (tid & 3) << 2;      // 0,4,8,12
    const int bRow = tid >> 4;            // 0..15
    const int bCol = (tid & 15) << 2;     // 0..60
    const int mbase = (tid >> 4) << 3;    // thread M offset (x8)
    const int nbase = (tid & 15) << 2;    // thread N offset (x4)

    for (int k0 = 0; k0 < KP; k0 += BKK) {
        float4 av0 = *reinterpret_cast<const float4*>(&A[(row0 + aRow) * KP + k0 + aCol]);
        float4 av1 = *reinterpret_cast<const float4*>(&A[(row0 + aRow + 64) * KP + k0 + aCol]);
        float4 bv  = *reinterpret_cast<const float4*>(&Bm[(k0 + bRow) * ldb + col0 + bCol]);
        As[aCol + 0][aRow] = av0.x; As[aCol + 1][aRow] = av0.y;
        As[aCol + 2][aRow] = av0.z; As[aCol + 3][aRow] = av0.w;
        As[aCol + 0][aRow + 64] = av1.x; As[aCol + 1][aRow + 64] = av1.y;
        As[aCol + 2][aRow + 64] = av1.z; As[aCol + 3][aRow + 64] = av1.w;
        *reinterpret_cast<float4*>(&Bs[bRow][bCol]) = bv;
        __syncthreads();
#pragma unroll
        for (int k = 0; k < BKK; k++) {
            float4 a0 = *reinterpret_cast<const float4*>(&As[k][mbase]);
            float4 a1 = *reinterpret_cast<const float4*>(&As[k][mbase + 4]);
            float4 b0 = *reinterpret_cast<const float4*>(&Bs[k][nbase]);
            float av[8] = {a0.x, a0.y, a0.z, a0.w, a1.x, a1.y, a1.z, a1.w};
            float bb[4] = {b0.x, b0.y, b0.z, b0.w};
#pragma unroll
            for (int i = 0; i < 8; i++)
#pragma unroll
                for (int j = 0; j < 4; j++) acc[i][j] += av[i] * bb[j];
        }
        __syncthreads();
    }

    // fused epilogue (x-projection has K=10, negligible)
#pragma unroll
    for (int i = 0; i < 8; i++) {
        const int r = row0 + mbase + i;
        const float* xp = &g_xs[(t * BBATCH + r) * EMB];
        float xv[EMB];
#pragma unroll
        for (int e = 0; e < EMB; e++) xv[e] = xp[e];
        if (MODE == 1) {
#pragma unroll
            for (int q = 0; q < 4; q++) {
                const int n = col0 + nbase + q;
                float xm = 0.f;
#pragma unroll
                for (int e = 0; e < EMB; e++) xm += xv[e] * g_wmxn[e * NP1 + n];
                if (n < H) g_m[r * KP + n] = xm * acc[i][q];
            }
        } else {
#pragma unroll
            for (int q = 0; q < 4; q++) {
                const int n = col0 + nbase + q;
                if (n < FH) {
                    float s = acc[i][q] + bias[n];
#pragma unroll
                    for (int e = 0; e < EMB; e++) s += xv[e] * g_wxn[e * NP2 + n];
                    g_z[r * NP2 + n] = s;
                }
            }
        }
    }
}

// ---------------- gates + state update + snapshot ----------------
__device__ __forceinline__ float sigmf(float x) { return 1.f / (1.f + expf(-x)); }

__global__ void gates_kernel(int t, int Mt)
{
    int idx = blockIdx.x * blockDim.x + threadIdx.x;
    if (idx >= Mt * H) return;
    int row = idx / H;
    int j = idx - row * H;
    const float* zr = &g_z[row * NP2];
    float iv = zr[j];
    float fv = zr[H + j];
    float ov = zr[2 * H + j];
    float uv = zr[3 * H + j];
    float c = g_c[row * KP + j];
    c = sigmf(fv) * c + sigmf(iv) * tanhf(uv);
    float h = sigmf(ov) * tanhf(c);
    g_c[row * KP + j] = c;
    g_h[row * KP + j] = h;
    if (row < NB) {
        if (g_ti[row] == t) g_toth[row * H + j] = h;
    } else {
        int b = row - NB;
        if (g_ei[b] == t) g_epih[b * H + j] = h;
    }
}

// ---------------- classifier: concat -> lrelu/bn1 -> W1 -> lrelu/bn2 -> W2 ----------------
__global__ void classifier_kernel(
    const float* __restrict__ bn1g, const float* __restrict__ bn1b,
    const float* __restrict__ bn1m, const float* __restrict__ bn1v,
    const float* __restrict__ W1,  const float* __restrict__ b1,
    const float* __restrict__ bn2g, const float* __restrict__ bn2b,
    const float* __restrict__ bn2m, const float* __restrict__ bn2v,
    const float* __restrict__ W2,  const float* __restrict__ b2,
    float* __restrict__ out)
{
    __shared__ float xsh[2 * H];     // 3800
    __shared__ float ysh[FH / 20];   // 380
    __shared__ float red[256];
    const int b = blockIdx.x;
    const int tid = threadIdx.x;
    const int IC = 2 * H;        // 3800
    const int OC = IC / 10;      // 380

    for (int k = tid; k < IC; k += 256) {
        float v = (k < H) ? g_toth[b * H + k] : g_epih[b * H + (k - H)];
        v = (v >= 0.f) ? v : 0.3f * v;
        v = (v - bn1m[k]) / sqrtf(bn1v[k] + 1e-3f) * bn1g[k] + bn1b[k];
        xsh[k] = v;
    }
    __syncthreads();
    for (int col = tid; col < OC; col += 256) {
        float s = b1[col];
        for (int k = 0; k < IC; k++) s += xsh[k] * W1[k * OC + col];
        s = (s >= 0.f) ? s : 0.3f * s;
        s = (s - bn2m[col]) / sqrtf(bn2v[col] + 1e-3f) * bn2g[col] + bn2b[col];
        ysh[col] = s;
    }
    __syncthreads();
    float acc = 0.f;
    for (int k = tid; k < OC; k += 256) acc += ysh[k] * W2[k];
    red[tid] = acc;
    __syncthreads();
    for (int s = 128; s > 0; s >>= 1) {
        if (tid < s) red[tid] += red[tid + s];
        __syncthreads();
    }
    if (tid == 0) out[b] = red[0] + b2[0];
}

// ---------------- launch ----------------
extern "C" void kernel_launch(void* const* d_in, const int* in_sizes, int n_in,
                              void* d_out, int out_size)
{
    const int*   epi   = (const int*)  d_in[0];
    const int*   lft   = (const int*)  d_in[1];
    const int*   rgt   = (const int*)  d_in[2];
    const int*   tot   = (const int*)  d_in[3];
    const float* embed = (const float*)d_in[4];
    const float* wx    = (const float*)d_in[5];
    const float* wh    = (const float*)d_in[6];
    const float* wmx   = (const float*)d_in[7];
    const float* wmh   = (const float*)d_in[8];
    const float* bb    = (const float*)d_in[9];
    const float* gx    = (const float*)d_in[10];
    const float* gh    = (const float*)d_in[11];
    const float* gmx   = (const float*)d_in[12];
    const float* gmh   = (const float*)d_in[13];
    float* out = (float*)d_out;

    wnorm_kernel<<<(NP2 + 127) / 128, 128>>>(wh,  gh,  0);
    wnorm_kernel<<<(NP1 + 127) / 128, 128>>>(wmh, gmh, 1);
    wnorm_kernel<<<(NP2 + 127) / 128, 128>>>(wx,  gx,  2);
    wnorm_kernel<<<(NP1 + 127) / 128, 128>>>(wmx, gmx, 3);
    lengths_kernel<<<1, 256>>>(epi, lft, rgt);
    const int embN = TSTEPS * NB * EMB + TEPI * NB * EMB;
    embed_kernel<<<(embN + 255) / 256, 256>>>(epi, tot, embed);
    init_kernel<<<(BBATCH * KP + 255) / 256, 256>>>();

    for (int t = 0; t < TSTEPS; t++) {
        const int Mt = (t < TEPI) ? BBATCH : NB;
        dim3 g1(NP1 / BN, Mt / BM);
        gemm_step<1><<<g1, 256>>>(t, nullptr);
        dim3 g2(NP2 / BN, Mt / BM);
        gemm_step<2><<<g2, 256>>>(t, bb);
        gates_kernel<<<(Mt * H + 255) / 256, 256>>>(t, Mt);
    }

    classifier_kernel<<<NB, 256>>>(
        (const float*)d_in[14], (const float*)d_in[15], (const float*)d_in[16], (const float*)d_in[17],
        (const float*)d_in[18], (const float*)d_in[19],
        (const float*)d_in[20], (const float*)d_in[21], (const float*)d_in[22], (const float*)d_in[23],
        (const float*)d_in[24], (const float*)d_in[25], out);
}